// round 3
// baseline (speedup 1.0000x reference)
#include <cuda_runtime.h>
#include <cstdint>

#define T_STEPS 2048
#define BATCH   64
#define HID     256
#define MROWS   (T_STEPS * BATCH)   // 131072

__device__ float g_buf0[(size_t)MROWS * HID];
__device__ float g_buf1[(size_t)MROWS * HID];

// ---------------------------------------------------------------------------
// f32x2 packed helpers
// ---------------------------------------------------------------------------
union F4U { float4 v; unsigned long long u[2]; };

__device__ __forceinline__ unsigned long long ffma2(
    unsigned long long a, unsigned long long b, unsigned long long c)
{
    unsigned long long d;
    asm("fma.rn.f32x2 %0, %1, %2, %3;" : "=l"(d) : "l"(a), "l"(b), "l"(c));
    return d;
}
__device__ __forceinline__ unsigned long long pk2(float lo, float hi)
{
    unsigned long long r;
    asm("mov.b64 %0, {%1, %2};" : "=l"(r) : "f"(lo), "f"(hi));
    return r;
}
__device__ __forceinline__ float2 up2(unsigned long long v)
{
    float2 r;
    asm("mov.b64 {%0, %1}, %2;" : "=f"(r.x), "=f"(r.y) : "l"(v));
    return r;
}

// ---------------------------------------------------------------------------
// GEMM + bias:  C[M,256] = A[M,256] @ W[256,256]^T + (b1+b2)
// BM=128, BN=64, BK=16, TM=8, TN=4, 256 threads. FFMA2 inner loop.
// ---------------------------------------------------------------------------
__global__ __launch_bounds__(256) void gemm_bias_kernel(
    const float* __restrict__ A,
    const float* __restrict__ W,      // [N,K] row-major
    const float* __restrict__ b1,
    const float* __restrict__ b2,
    float* __restrict__ C)
{
    __shared__ float As[16][132];   // [k][m], padded
    __shared__ float Ws[16][68];    // [k][n], padded

    const int tid = threadIdx.x;
    const int bm  = blockIdx.x * 128;
    const int bn  = blockIdx.y * 64;
    const int tx  = tid & 15;       // n-sub -> 4 cols
    const int ty  = tid >> 4;       // m-sub -> 8 rows

    const int arow = tid >> 2;      // 0..63
    const int akq  = tid & 3;       // float4 slot within 16-wide k chunk

    // acc2[ip][j]: packed pair (row 2ip, row 2ip+1) for col j
    unsigned long long acc2[4][4];
    #pragma unroll
    for (int ip = 0; ip < 4; ip++)
        #pragma unroll
        for (int j = 0; j < 4; j++) acc2[ip][j] = 0ull;

    for (int k0 = 0; k0 < 256; k0 += 16) {
        {
            float4 v = *reinterpret_cast<const float4*>(
                &A[(size_t)(bm + arow) * 256 + k0 + akq * 4]);
            As[akq*4+0][arow] = v.x; As[akq*4+1][arow] = v.y;
            As[akq*4+2][arow] = v.z; As[akq*4+3][arow] = v.w;
            float4 v2 = *reinterpret_cast<const float4*>(
                &A[(size_t)(bm + arow + 64) * 256 + k0 + akq * 4]);
            As[akq*4+0][arow+64] = v2.x; As[akq*4+1][arow+64] = v2.y;
            As[akq*4+2][arow+64] = v2.z; As[akq*4+3][arow+64] = v2.w;
        }
        {
            float4 v = *reinterpret_cast<const float4*>(
                &W[(size_t)(bn + arow) * 256 + k0 + akq * 4]);
            Ws[akq*4+0][arow] = v.x; Ws[akq*4+1][arow] = v.y;
            Ws[akq*4+2][arow] = v.z; Ws[akq*4+3][arow] = v.w;
        }
        __syncthreads();

        #pragma unroll
        for (int k = 0; k < 16; k++) {
            F4U a03, a47;
            a03.v = *reinterpret_cast<const float4*>(&As[k][ty * 8]);
            a47.v = *reinterpret_cast<const float4*>(&As[k][ty * 8 + 4]);
            float4 wv = *reinterpret_cast<const float4*>(&Ws[k][tx * 4]);
            unsigned long long wd[4];
            wd[0] = pk2(wv.x, wv.x); wd[1] = pk2(wv.y, wv.y);
            wd[2] = pk2(wv.z, wv.z); wd[3] = pk2(wv.w, wv.w);
            #pragma unroll
            for (int j = 0; j < 4; j++) {
                acc2[0][j] = ffma2(a03.u[0], wd[j], acc2[0][j]);
                acc2[1][j] = ffma2(a03.u[1], wd[j], acc2[1][j]);
                acc2[2][j] = ffma2(a47.u[0], wd[j], acc2[2][j]);
                acc2[3][j] = ffma2(a47.u[1], wd[j], acc2[3][j]);
            }
        }
        __syncthreads();
    }

    float bias[4];
    #pragma unroll
    for (int j = 0; j < 4; j++) {
        int n = bn + tx * 4 + j;
        bias[j] = b1[n] + b2[n];
    }

    #pragma unroll
    for (int ip = 0; ip < 4; ip++) {
        float2 p[4];
        #pragma unroll
        for (int j = 0; j < 4; j++) p[j] = up2(acc2[ip][j]);
        int row0 = bm + ty * 8 + 2 * ip;
        float4 o0, o1;
        o0.x = p[0].x + bias[0]; o0.y = p[1].x + bias[1];
        o0.z = p[2].x + bias[2]; o0.w = p[3].x + bias[3];
        o1.x = p[0].y + bias[0]; o1.y = p[1].y + bias[1];
        o1.z = p[2].y + bias[2]; o1.w = p[3].y + bias[3];
        *reinterpret_cast<float4*>(&C[(size_t)row0 * 256 + bn + tx * 4]) = o0;
        *reinterpret_cast<float4*>(&C[(size_t)(row0+1) * 256 + bn + tx * 4]) = o1;
    }
}

// ---------------------------------------------------------------------------
// Recurrent scan: one CTA per batch element, 256 threads, thread j owns h[j].
// W_hh row j: k in [0,192) in registers (96 packed f32x2), k in [192,256) in
// smem (16 float4/thread, padded stride 17 -> conflict-free within LDS phases).
// h double-buffered -> one barrier per step. All MACs via fma.rn.f32x2.
// ---------------------------------------------------------------------------
__global__ __launch_bounds__(256, 1) void rnn_layer_kernel(
    const float* __restrict__ xp,    // [T, B, H] precomputed input + biases
    const float* __restrict__ Whh,   // [H, H] row-major
    float* __restrict__ out)         // [T, B, H]
{
    extern __shared__ float4 Wt[];             // [256][17] float4 = 69632 B
    __shared__ __align__(16) float hbuf[2][HID];

    const int b = blockIdx.x;
    const int j = threadIdx.x;

    // One-time: load W row j -> 192 floats as 96 packed pairs in regs,
    // last 64 floats -> smem.
    unsigned long long w2[96];
    const float4* wrow = reinterpret_cast<const float4*>(Whh + (size_t)j * HID);
    #pragma unroll
    for (int i = 0; i < 48; i++) {
        F4U v; v.v = wrow[i];
        w2[2*i]   = v.u[0];
        w2[2*i+1] = v.u[1];
    }
    #pragma unroll
    for (int i = 0; i < 16; i++)
        Wt[j * 17 + i] = wrow[48 + i];

    hbuf[0][j] = 0.f;
    __syncthreads();

    const float4* wsrow  = &Wt[j * 17];
    const float*  xptr   = xp  + (size_t)b * HID + j;
    float*        optr   = out + (size_t)b * HID + j;
    const size_t  stride = (size_t)BATCH * HID;

    int cur = 0;
    for (int t = 0; t < T_STEPS; t++) {
        float xv = xptr[(size_t)t * stride];   // early LDG, hidden by k-loop

        const float4* h4 = reinterpret_cast<const float4*>(hbuf[cur]);
        unsigned long long a0 = 0ull, a1 = 0ull, a2 = 0ull, a3 = 0ull;

        #pragma unroll
        for (int i = 0; i < 48; i += 2) {      // k in [0,192): W in regs
            F4U hv0; hv0.v = h4[i];
            a0 = ffma2(w2[2*i],   hv0.u[0], a0);
            a1 = ffma2(w2[2*i+1], hv0.u[1], a1);
            F4U hv1; hv1.v = h4[i+1];
            a2 = ffma2(w2[2*i+2], hv1.u[0], a2);
            a3 = ffma2(w2[2*i+3], hv1.u[1], a3);
        }
        #pragma unroll
        for (int i = 0; i < 16; i += 2) {      // k in [192,256): W in smem
            F4U wv0; wv0.v = wsrow[i];
            F4U hv0; hv0.v = h4[48 + i];
            a0 = ffma2(wv0.u[0], hv0.u[0], a0);
            a1 = ffma2(wv0.u[1], hv0.u[1], a1);
            F4U wv1; wv1.v = wsrow[i+1];
            F4U hv1; hv1.v = h4[49 + i];
            a2 = ffma2(wv1.u[0], hv1.u[0], a2);
            a3 = ffma2(wv1.u[1], hv1.u[1], a3);
        }

        float2 s0 = up2(a0), s1 = up2(a1), s2 = up2(a2), s3 = up2(a3);
        float sum = ((s0.x + s0.y) + (s1.x + s1.y))
                  + ((s2.x + s2.y) + (s3.x + s3.y)) + xv;
        float h = tanhf(sum);

        hbuf[cur ^ 1][j] = h;
        optr[(size_t)t * stride] = h;
        __syncthreads();                       // writes drained + visible
        cur ^= 1;
    }
}

// ---------------------------------------------------------------------------
extern "C" void kernel_launch(void* const* d_in, const int* in_sizes, int n_in,
                              void* d_out, int out_size)
{
    const float* x     = (const float*)d_in[0];
    const float* W_ih0 = (const float*)d_in[1];
    const float* W_hh0 = (const float*)d_in[2];
    const float* b_ih0 = (const float*)d_in[3];
    const float* b_hh0 = (const float*)d_in[4];
    const float* W_ih1 = (const float*)d_in[5];
    const float* W_hh1 = (const float*)d_in[6];
    const float* b_ih1 = (const float*)d_in[7];
    const float* b_hh1 = (const float*)d_in[8];
    float* out = (float*)d_out;

    float *buf0, *buf1;
    cudaGetSymbolAddress((void**)&buf0, g_buf0);
    cudaGetSymbolAddress((void**)&buf1, g_buf1);

    const int RNN_SMEM = 256 * 17 * 16;  // 69632 B dynamic smem
    cudaFuncSetAttribute(rnn_layer_kernel,
                         cudaFuncAttributeMaxDynamicSharedMemorySize, RNN_SMEM);

    dim3 ggrid(MROWS / 128, 256 / 64);

    // Phase A: xp0 = x @ W_ih0^T + (b_ih0 + b_hh0)
    gemm_bias_kernel<<<ggrid, 256>>>(x, W_ih0, b_ih0, b_hh0, buf0);
    // Phase B: layer-1 scan -> h1
    rnn_layer_kernel<<<BATCH, 256, RNN_SMEM>>>(buf0, W_hh0, buf1);
    // Phase C: xp1 = h1 @ W_ih1^T + (b_ih1 + b_hh1)
    gemm_bias_kernel<<<ggrid, 256>>>(buf1, W_ih1, b_ih1, b_hh1, buf0);
    // Phase D: layer-2 scan -> output
    rnn_layer_kernel<<<BATCH, 256, RNN_SMEM>>>(buf0, W_hh1, out);
}

// round 4
// speedup vs baseline: 1.3488x; 1.3488x over previous
#include <cuda_runtime.h>
#include <cstdint>

#define T_STEPS 2048
#define BATCH   64
#define HID     256
#define MROWS   (T_STEPS * BATCH)   // 131072
#define NGW     20                  // GEMM worker CTAs (148 - 128)
#define NCHUNK  1024                // 2-timestep row chunks of 128 rows
#define NTILE   (NCHUNK * 4)        // (chunk, n-tile) work items

__device__ float g_buf0[(size_t)MROWS * HID];   // xp0
__device__ float g_buf1[(size_t)MROWS * HID];   // h1
__device__ float g_buf2[(size_t)MROWS * HID];   // xp1
__device__ int   g_prog1[BATCH];                // layer-1 scan progress (t+1)
__device__ int   g_midflag[NTILE];              // xp1 tile-done flags

// ---------------------------------------------------------------------------
// helpers
// ---------------------------------------------------------------------------
union F4U { float4 v; unsigned long long u[2]; };

__device__ __forceinline__ unsigned long long ffma2(
    unsigned long long a, unsigned long long b, unsigned long long c)
{
    unsigned long long d;
    asm("fma.rn.f32x2 %0, %1, %2, %3;" : "=l"(d) : "l"(a), "l"(b), "l"(c));
    return d;
}
__device__ __forceinline__ unsigned long long pk2(float lo, float hi)
{
    unsigned long long r;
    asm("mov.b64 %0, {%1, %2};" : "=l"(r) : "f"(lo), "f"(hi));
    return r;
}
__device__ __forceinline__ float2 up2(unsigned long long v)
{
    float2 r;
    asm("mov.b64 {%0, %1}, %2;" : "=f"(r.x), "=f"(r.y) : "l"(v));
    return r;
}
__device__ __forceinline__ int ld_acq(const int* p)
{
    int v;
    asm volatile("ld.acquire.gpu.global.b32 %0, [%1];" : "=r"(v) : "l"(p) : "memory");
    return v;
}
__device__ __forceinline__ void st_rel(int* p, int v)
{
    asm volatile("st.release.gpu.global.b32 [%0], %1;" :: "l"(p), "r"(v) : "memory");
}

// ---------------------------------------------------------------------------
// GEMM tile body: C[128, bn:bn+64] = A[128,256] @ W^T + (b1+b2).
// Called by all 256 threads of a CTA. Contains __syncthreads.
// ---------------------------------------------------------------------------
__device__ __forceinline__ void gemm_tile(
    const float* __restrict__ Arows,   // base of 128x256 row block
    const float* __restrict__ W,       // [256,256] row-major
    const float* __restrict__ b1,
    const float* __restrict__ b2,
    float* __restrict__ Crows,         // base of 128x256 row block
    int bn)
{
    __shared__ float As[16][132];
    __shared__ float Ws[16][68];

    const int tid = threadIdx.x;
    const int tx  = tid & 15;
    const int ty  = tid >> 4;
    const int arow = tid >> 2;
    const int akq  = tid & 3;

    unsigned long long acc2[4][4];
    #pragma unroll
    for (int ip = 0; ip < 4; ip++)
        #pragma unroll
        for (int j = 0; j < 4; j++) acc2[ip][j] = 0ull;

    for (int k0 = 0; k0 < 256; k0 += 16) {
        {
            float4 v = *reinterpret_cast<const float4*>(
                &Arows[(size_t)arow * 256 + k0 + akq * 4]);
            As[akq*4+0][arow] = v.x; As[akq*4+1][arow] = v.y;
            As[akq*4+2][arow] = v.z; As[akq*4+3][arow] = v.w;
            float4 v2 = *reinterpret_cast<const float4*>(
                &Arows[(size_t)(arow + 64) * 256 + k0 + akq * 4]);
            As[akq*4+0][arow+64] = v2.x; As[akq*4+1][arow+64] = v2.y;
            As[akq*4+2][arow+64] = v2.z; As[akq*4+3][arow+64] = v2.w;
        }
        {
            float4 v = *reinterpret_cast<const float4*>(
                &W[(size_t)(bn + arow) * 256 + k0 + akq * 4]);
            Ws[akq*4+0][arow] = v.x; Ws[akq*4+1][arow] = v.y;
            Ws[akq*4+2][arow] = v.z; Ws[akq*4+3][arow] = v.w;
        }
        __syncthreads();

        #pragma unroll
        for (int k = 0; k < 16; k++) {
            F4U a03, a47;
            a03.v = *reinterpret_cast<const float4*>(&As[k][ty * 8]);
            a47.v = *reinterpret_cast<const float4*>(&As[k][ty * 8 + 4]);
            float4 wv = *reinterpret_cast<const float4*>(&Ws[k][tx * 4]);
            unsigned long long wd[4];
            wd[0] = pk2(wv.x, wv.x); wd[1] = pk2(wv.y, wv.y);
            wd[2] = pk2(wv.z, wv.z); wd[3] = pk2(wv.w, wv.w);
            #pragma unroll
            for (int j = 0; j < 4; j++) {
                acc2[0][j] = ffma2(a03.u[0], wd[j], acc2[0][j]);
                acc2[1][j] = ffma2(a03.u[1], wd[j], acc2[1][j]);
                acc2[2][j] = ffma2(a47.u[0], wd[j], acc2[2][j]);
                acc2[3][j] = ffma2(a47.u[1], wd[j], acc2[3][j]);
            }
        }
        __syncthreads();
    }

    float bias[4];
    #pragma unroll
    for (int j = 0; j < 4; j++) {
        int n = bn + tx * 4 + j;
        bias[j] = b1[n] + b2[n];
    }

    #pragma unroll
    for (int ip = 0; ip < 4; ip++) {
        float2 p[4];
        #pragma unroll
        for (int j = 0; j < 4; j++) p[j] = up2(acc2[ip][j]);
        int row0 = ty * 8 + 2 * ip;
        float4 o0, o1;
        o0.x = p[0].x + bias[0]; o0.y = p[1].x + bias[1];
        o0.z = p[2].x + bias[2]; o0.w = p[3].x + bias[3];
        o1.x = p[0].y + bias[0]; o1.y = p[1].y + bias[1];
        o1.z = p[2].y + bias[2]; o1.w = p[3].y + bias[3];
        *reinterpret_cast<float4*>(&Crows[(size_t)row0 * 256 + bn + tx * 4]) = o0;
        *reinterpret_cast<float4*>(&Crows[(size_t)(row0+1) * 256 + bn + tx * 4]) = o1;
    }
}

// ---------------------------------------------------------------------------
// Standalone GEMM kernel (phase A: xp0)
// ---------------------------------------------------------------------------
__global__ __launch_bounds__(256) void gemm_bias_kernel(
    const float* __restrict__ A, const float* __restrict__ W,
    const float* __restrict__ b1, const float* __restrict__ b2,
    float* __restrict__ C)
{
    gemm_tile(A + (size_t)blockIdx.x * 128 * 256, W, b1, b2,
              C + (size_t)blockIdx.x * 128 * 256, blockIdx.y * 64);
}

// ---------------------------------------------------------------------------
// Flag reset kernel (graph-replay safe)
// ---------------------------------------------------------------------------
__global__ void zero_flags_kernel()
{
    int t = threadIdx.x;
    if (t < BATCH) g_prog1[t] = 0;
    for (int i = t; i < NTILE; i += blockDim.x) g_midflag[i] = 0;
}

// ---------------------------------------------------------------------------
// Scan role: one CTA per batch element. W_hh row j: 128 floats in regs
// (64 packed f32x2), 128 floats in smem. Double-buffered h, 1 barrier/step.
// Optional: publish progress (layer 1) / poll tile flags (layer 2).
// ---------------------------------------------------------------------------
__device__ __forceinline__ void scan_role(
    const float* __restrict__ xp, const float* __restrict__ Whh,
    float* __restrict__ out, int b,
    int* prog_out, const int* poll_flags,
    float4* Wt /* dynamic smem [256][33] */)
{
    __shared__ __align__(16) float hbuf[2][HID];
    const int j = threadIdx.x;

    unsigned long long w2[64];
    const float4* wrow = reinterpret_cast<const float4*>(Whh + (size_t)j * HID);
    #pragma unroll
    for (int i = 0; i < 32; i++) {
        F4U v; v.v = wrow[i];
        w2[2*i] = v.u[0]; w2[2*i+1] = v.u[1];
    }
    #pragma unroll
    for (int i = 0; i < 32; i++)
        Wt[j * 33 + i] = wrow[32 + i];

    hbuf[0][j] = 0.f;
    __syncthreads();

    const float4* wsrow  = &Wt[j * 33];
    const float*  xptr   = xp  + (size_t)b * HID + j;
    float*        optr   = out + (size_t)b * HID + j;
    const size_t  stride = (size_t)BATCH * HID;

    int cur = 0;
    for (int t = 0; t < T_STEPS; t++) {
        if (poll_flags && (t & 1) == 0) {
            int c = t >> 1;
            if (j < 4)
                while (ld_acq(&poll_flags[c * 4 + j]) == 0) { }
            __syncthreads();
        }

        float xv = xptr[(size_t)t * stride];

        const float4* h4 = reinterpret_cast<const float4*>(hbuf[cur]);
        unsigned long long a0 = 0ull, a1 = 0ull, a2 = 0ull, a3 = 0ull;

        #pragma unroll
        for (int i = 0; i < 32; i += 2) {      // k in [0,128): W in regs
            F4U hv0; hv0.v = h4[i];
            a0 = ffma2(w2[2*i],   hv0.u[0], a0);
            a1 = ffma2(w2[2*i+1], hv0.u[1], a1);
            F4U hv1; hv1.v = h4[i+1];
            a2 = ffma2(w2[2*i+2], hv1.u[0], a2);
            a3 = ffma2(w2[2*i+3], hv1.u[1], a3);
        }
        #pragma unroll
        for (int i = 0; i < 32; i += 2) {      // k in [128,256): W in smem
            F4U wv0; wv0.v = wsrow[i];
            F4U hv0; hv0.v = h4[32 + i];
            a0 = ffma2(wv0.u[0], hv0.u[0], a0);
            a1 = ffma2(wv0.u[1], hv0.u[1], a1);
            F4U wv1; wv1.v = wsrow[i+1];
            F4U hv1; hv1.v = h4[33 + i];
            a2 = ffma2(wv1.u[0], hv1.u[0], a2);
            a3 = ffma2(wv1.u[1], hv1.u[1], a3);
        }

        float2 s0 = up2(a0), s1 = up2(a1), s2 = up2(a2), s3 = up2(a3);
        float sum = ((s0.x + s0.y) + (s1.x + s1.y))
                  + ((s2.x + s2.y) + (s3.x + s3.y)) + xv;
        float h = tanhf(sum);

        hbuf[cur ^ 1][j] = h;
        optr[(size_t)t * stride] = h;
        __syncthreads();
        if (prog_out && j == 0) st_rel(prog_out, t + 1);
        cur ^= 1;
    }
}

// ---------------------------------------------------------------------------
// Persistent pipeline mega-kernel: 148 CTAs.
//   bid 0..63   : layer-1 scan (xp0 -> h1), publish g_prog1[b]
//   bid 64..127 : layer-2 scan (xp1 -> out), poll g_midflag
//   bid 128..147: xp1 GEMM workers (h1 @ W_ih1^T + bias), publish g_midflag
// ---------------------------------------------------------------------------
__global__ __launch_bounds__(256, 1) void pipeline_kernel(
    const float* __restrict__ W_hh0,
    const float* __restrict__ W_ih1,
    const float* __restrict__ b_ih1,
    const float* __restrict__ b_hh1,
    const float* __restrict__ W_hh1,
    float* __restrict__ out)
{
    extern __shared__ float4 Wt[];   // [256][33] float4 for scan roles
    const int bid = blockIdx.x;

    if (bid < 64) {
        scan_role(g_buf0, W_hh0, g_buf1, bid, &g_prog1[bid], nullptr, Wt);
    } else if (bid < 128) {
        scan_role(g_buf2, W_hh1, out, bid - 64, nullptr, g_midflag, Wt);
    } else {
        const int wid = bid - 128;
        const int tid = threadIdx.x;
        for (int w = wid; w < NTILE; w += NGW) {
            int c = w >> 2;          // 2-timestep row chunk
            int n = w & 3;           // 64-wide n tile
            if (tid < BATCH)
                while (ld_acq(&g_prog1[tid]) < 2 * c + 2) { }
            __syncthreads();
            gemm_tile(g_buf1 + (size_t)c * 128 * 256, W_ih1, b_ih1, b_hh1,
                      g_buf2 + (size_t)c * 128 * 256, n * 64);
            __syncthreads();
            if (tid == 0) st_rel(&g_midflag[w], 1);
        }
    }
}

// ---------------------------------------------------------------------------
extern "C" void kernel_launch(void* const* d_in, const int* in_sizes, int n_in,
                              void* d_out, int out_size)
{
    const float* x     = (const float*)d_in[0];
    const float* W_ih0 = (const float*)d_in[1];
    const float* W_hh0 = (const float*)d_in[2];
    const float* b_ih0 = (const float*)d_in[3];
    const float* b_hh0 = (const float*)d_in[4];
    const float* W_ih1 = (const float*)d_in[5];
    const float* W_hh1 = (const float*)d_in[6];
    const float* b_ih1 = (const float*)d_in[7];
    const float* b_hh1 = (const float*)d_in[8];
    float* out = (float*)d_out;

    float* buf0;
    cudaGetSymbolAddress((void**)&buf0, g_buf0);

    const int PIPE_SMEM = 256 * 33 * 16;  // 135168 B
    cudaFuncSetAttribute(pipeline_kernel,
                         cudaFuncAttributeMaxDynamicSharedMemorySize, PIPE_SMEM);

    // Reset progress flags (graph replays re-run this)
    zero_flags_kernel<<<1, 256>>>();

    // Phase A: xp0 = x @ W_ih0^T + (b_ih0 + b_hh0), full-width grid
    gemm_bias_kernel<<<dim3(NCHUNK, 4), 256>>>(x, W_ih0, b_ih0, b_hh0, buf0);

    // Phases B/C/D fused: persistent pipeline across 148 SMs
    pipeline_kernel<<<148, 256, PIPE_SMEM>>>(W_hh0, W_ih1, b_ih1, b_hh1,
                                             W_hh1, out);
}